// round 1
// baseline (speedup 1.0000x reference)
#include <cuda_runtime.h>
#include <math.h>

#define Bsz 64
#define Ssz 128
#define Hsz 1024
#define Vsz 32000
#define Tsz 10
#define H3  (3*Hsz)

// ---------------- device scratch (no allocations allowed) ----------------
__device__ float g_Uk[Bsz*Ssz*Hsz];   // 33.5 MB
__device__ float g_h [2*Bsz*Hsz];     // ping-pong hidden
__device__ float g_q [Bsz*Hsz];
__device__ float g_x [Bsz*2*Hsz];     // [emb | ctx]
__device__ float g_gi[Bsz*H3];
__device__ float g_gh[Bsz*H3];
__device__ float g_sc[Bsz*Ssz];

// ---------------- GEMM: C[M,N] (+)= A[M,K] * W[N,K]^T (+ bias) ----------------
// block tile 64(M) x 128(N), 256 threads, per-thread 4x4... (4M x 8N), K-chunk 16.
// grid = (N/128, nSplits, M/64). If nSplits>1: C must be pre-zeroed; atomicAdd,
// bias added only by blockIdx.y==0. If nSplits==1: direct store with bias.
__global__ __launch_bounds__(256)
void gemm_tn(const float* __restrict__ A, const float* __restrict__ W,
             const float* __restrict__ bias, float* __restrict__ C,
             int K, int ldc, int kPerSplit, int nSplits)
{
    __shared__ float As[16][64];
    __shared__ float Ws[16][128];

    const int t  = threadIdx.x;
    const int m0 = blockIdx.z * 64;
    const int n0 = blockIdx.x * 128;
    const int kb0 = blockIdx.y * kPerSplit;
    const int tm = t >> 4;        // 0..15 -> row group *4
    const int tn = t & 15;        // 0..15 -> col group *8

    float acc[4][8];
    #pragma unroll
    for (int i = 0; i < 4; i++)
        #pragma unroll
        for (int j = 0; j < 8; j++) acc[i][j] = 0.f;

    const int am = t >> 2;              // 0..63
    const int ak = (t & 3) << 2;        // 0,4,8,12
    const int wn = t >> 1;              // 0..127
    const int wk = (t & 1) << 3;        // 0,8

    const float* Ap = A + (size_t)(m0 + am) * K + ak;
    const float* Wp = W + (size_t)(n0 + wn) * K + wk;

    for (int kb = kb0; kb < kb0 + kPerSplit; kb += 16) {
        float4 av = *(const float4*)(Ap + kb);
        float4 w0 = *(const float4*)(Wp + kb);
        float4 w1 = *(const float4*)(Wp + kb + 4);
        __syncthreads();
        As[ak+0][am] = av.x; As[ak+1][am] = av.y;
        As[ak+2][am] = av.z; As[ak+3][am] = av.w;
        Ws[wk+0][wn] = w0.x; Ws[wk+1][wn] = w0.y;
        Ws[wk+2][wn] = w0.z; Ws[wk+3][wn] = w0.w;
        Ws[wk+4][wn] = w1.x; Ws[wk+5][wn] = w1.y;
        Ws[wk+6][wn] = w1.z; Ws[wk+7][wn] = w1.w;
        __syncthreads();
        #pragma unroll
        for (int kk = 0; kk < 16; kk++) {
            float4 a  = *(const float4*)(&As[kk][tm << 2]);
            float4 b0 = *(const float4*)(&Ws[kk][tn << 3]);
            float4 b1 = *(const float4*)(&Ws[kk][(tn << 3) + 4]);
            float as4[4] = {a.x, a.y, a.z, a.w};
            float bs8[8] = {b0.x, b0.y, b0.z, b0.w, b1.x, b1.y, b1.z, b1.w};
            #pragma unroll
            for (int i = 0; i < 4; i++)
                #pragma unroll
                for (int j = 0; j < 8; j++)
                    acc[i][j] = fmaf(as4[i], bs8[j], acc[i][j]);
        }
    }

    #pragma unroll
    for (int i = 0; i < 4; i++) {
        const int m = m0 + (tm << 2) + i;
        #pragma unroll
        for (int j = 0; j < 8; j++) {
            const int n = n0 + (tn << 3) + j;
            float v = acc[i][j];
            if (nSplits == 1) {
                C[(size_t)m * ldc + n] = v + (bias ? bias[n] : 0.f);
            } else {
                if (blockIdx.y == 0 && bias) v += bias[n];
                atomicAdd(&C[(size_t)m * ldc + n], v);
            }
        }
    }
}

// ---------------- helpers ----------------
__global__ void copy_k(const float* __restrict__ src, float* __restrict__ dst, int n)
{
    int i = blockIdx.x * blockDim.x + threadIdx.x;
    if (i < n) dst[i] = src[i];
}

__global__ void zero3_k(float* __restrict__ q, float* __restrict__ gi, float* __restrict__ gh)
{
    int i = blockIdx.x * blockDim.x + threadIdx.x;   // grid sized to Bsz*H3 exactly
    if (i < Bsz * Hsz) q[i] = 0.f;
    gi[i] = 0.f;
    gh[i] = 0.f;
}

__global__ void emb_k(const float* __restrict__ embW, const int* __restrict__ target,
                      int t, float* __restrict__ x)
{
    int b = blockIdx.x;
    int h = blockIdx.y * 256 + threadIdx.x;
    int tok = (t == 0) ? 0 : target[b * Tsz + (t - 1)];
    x[b * 2 * Hsz + h] = embW[(size_t)tok * Hsz + h];
}

// scores[b,s] = Va . tanh(q[b] + Uk[b,s]) + Va_b   (one warp per (b,s))
__global__ __launch_bounds__(256)
void attn_scores_k(const float* __restrict__ Uk, const float* __restrict__ q,
                   const float* __restrict__ Va, const float* __restrict__ Vab,
                   float* __restrict__ scores)
{
    int b = blockIdx.x;
    int s = blockIdx.y * 8 + (threadIdx.x >> 5);
    int lane = threadIdx.x & 31;
    const float* ukr = Uk + ((size_t)b * Ssz + s) * Hsz;
    const float* qr  = q + b * Hsz;
    float acc = 0.f;
    for (int h = lane * 4; h < Hsz; h += 128) {
        float4 u  = *(const float4*)(ukr + h);
        float4 qv = *(const float4*)(qr + h);
        float4 vv = *(const float4*)(Va + h);
        acc += vv.x * tanhf(qv.x + u.x);
        acc += vv.y * tanhf(qv.y + u.y);
        acc += vv.z * tanhf(qv.z + u.z);
        acc += vv.w * tanhf(qv.w + u.w);
    }
    #pragma unroll
    for (int o = 16; o; o >>= 1) acc += __shfl_xor_sync(0xffffffffu, acc, o);
    if (!lane) scores[b * Ssz + s] = acc + Vab[0];
}

// softmax over S, write attns slice (chunk 0 only), ctx[b,h] = sum_s w*E[b,s,h]
// grid (B, H/128), block 128
__global__ __launch_bounds__(128)
void attn_ctx_k(const float* __restrict__ sc, const float* __restrict__ E,
                float* __restrict__ x, float* __restrict__ attns, int t)
{
    __shared__ float wsm[Ssz];
    __shared__ float red[4];
    int b = blockIdx.x, tid = threadIdx.x;

    float v0 = sc[b * Ssz + tid];
    float m = v0;
    #pragma unroll
    for (int o = 16; o; o >>= 1) m = fmaxf(m, __shfl_xor_sync(0xffffffffu, m, o));
    if ((tid & 31) == 0) red[tid >> 5] = m;
    __syncthreads();
    float mx = fmaxf(fmaxf(red[0], red[1]), fmaxf(red[2], red[3]));
    __syncthreads();

    float e = expf(v0 - mx);
    float sm = e;
    #pragma unroll
    for (int o = 16; o; o >>= 1) sm += __shfl_xor_sync(0xffffffffu, sm, o);
    if ((tid & 31) == 0) red[tid >> 5] = sm;
    __syncthreads();
    float ssum = red[0] + red[1] + red[2] + red[3];

    float w = e / ssum;
    wsm[tid] = w;
    if (blockIdx.y == 0) attns[((size_t)b * Tsz + t) * Ssz + tid] = w;
    __syncthreads();

    int h = blockIdx.y * 128 + tid;
    const float* Eb = E + (size_t)b * Ssz * Hsz + h;
    float acc = 0.f;
    #pragma unroll 8
    for (int s2 = 0; s2 < Ssz; s2++) acc = fmaf(wsm[s2], Eb[(size_t)s2 * Hsz], acc);
    x[b * 2 * Hsz + Hsz + h] = acc;
}

__global__ void gates_k(const float* __restrict__ gi, const float* __restrict__ gh,
                        const float* __restrict__ hin, float* __restrict__ hout)
{
    int idx = blockIdx.x * blockDim.x + threadIdx.x;   // B*H
    int b = idx >> 10, j = idx & 1023;
    const float* gib = gi + b * H3;
    const float* ghb = gh + b * H3;
    float r = 1.f / (1.f + expf(-(gib[j]           + ghb[j])));
    float z = 1.f / (1.f + expf(-(gib[Hsz + j]     + ghb[Hsz + j])));
    float n = tanhf(gib[2 * Hsz + j] + r * ghb[2 * Hsz + j]);
    hout[idx] = (1.f - z) * n + z * hin[idx];
}

__global__ __launch_bounds__(256)
void lsm_k(float* __restrict__ out)
{
    __shared__ float red[8];
    float* p = out + (size_t)blockIdx.x * Vsz;
    int tid = threadIdx.x;

    float mx = -3.4e38f;
    for (int i = tid; i < Vsz; i += 256) mx = fmaxf(mx, p[i]);
    #pragma unroll
    for (int o = 16; o; o >>= 1) mx = fmaxf(mx, __shfl_xor_sync(0xffffffffu, mx, o));
    if ((tid & 31) == 0) red[tid >> 5] = mx;
    __syncthreads();
    mx = red[0];
    #pragma unroll
    for (int w = 1; w < 8; w++) mx = fmaxf(mx, red[w]);
    __syncthreads();

    float s = 0.f;
    for (int i = tid; i < Vsz; i += 256) s += expf(p[i] - mx);
    #pragma unroll
    for (int o = 16; o; o >>= 1) s += __shfl_xor_sync(0xffffffffu, s, o);
    if ((tid & 31) == 0) red[tid >> 5] = s;
    __syncthreads();
    s = 0.f;
    #pragma unroll
    for (int w = 0; w < 8; w++) s += red[w];
    float lse = mx + logf(s);

    for (int i = tid; i < Vsz; i += 256) p[i] -= lse;
}

// ---------------- launch ----------------
extern "C" void kernel_launch(void* const* d_in, const int* in_sizes, int n_in,
                              void* d_out, int out_size)
{
    const float* enc    = (const float*)d_in[0];
    const float* hidden = (const float*)d_in[1];
    const int*   target = (const int*)  d_in[2];
    const float* embW   = (const float*)d_in[3];
    const float* Wa_w   = (const float*)d_in[4];
    const float* Wa_b   = (const float*)d_in[5];
    const float* Ua_w   = (const float*)d_in[6];
    const float* Ua_b   = (const float*)d_in[7];
    const float* Va_w   = (const float*)d_in[8];
    const float* Va_b   = (const float*)d_in[9];
    const float* W_ih   = (const float*)d_in[10];
    const float* W_hh   = (const float*)d_in[11];
    const float* b_ih   = (const float*)d_in[12];
    const float* b_hh   = (const float*)d_in[13];
    const float* out_W  = (const float*)d_in[14];
    const float* out_b  = (const float*)d_in[15];

    float* out_lp = (float*)d_out;                        // [B,T,V]
    float* out_h  = out_lp + (size_t)Bsz * Tsz * Vsz;     // [1,B,H]
    float* out_at = out_h + (size_t)Bsz * Hsz;            // [B,T,S]

    float *Uk, *hb, *q, *x, *gi, *gh, *sc;
    cudaGetSymbolAddress((void**)&Uk, g_Uk);
    cudaGetSymbolAddress((void**)&hb, g_h);
    cudaGetSymbolAddress((void**)&q,  g_q);
    cudaGetSymbolAddress((void**)&x,  g_x);
    cudaGetSymbolAddress((void**)&gi, g_gi);
    cudaGetSymbolAddress((void**)&gh, g_gh);
    cudaGetSymbolAddress((void**)&sc, g_sc);
    float* h0 = hb;
    float* h1 = hb + Bsz * Hsz;

    // h <- hidden[0]
    copy_k<<<(Bsz * Hsz + 255) / 256, 256>>>(hidden, h0, Bsz * Hsz);

    // Uk[b,s,g] = E[b,s] . Ua_w[g] + Ua_b[g]   (M=8192, N=1024, K=1024)
    gemm_tn<<<dim3(Hsz / 128, 1, (Bsz * Ssz) / 64), 256>>>(
        enc, Ua_w, Ua_b, Uk, Hsz, Hsz, Hsz, 1);

    for (int t = 0; t < Tsz; t++) {
        float* hc = (t & 1) ? h1 : h0;
        float* hn = (t & 1) ? h0 : h1;

        zero3_k<<<(Bsz * H3) / 256, 256>>>(q, gi, gh);
        emb_k<<<dim3(Bsz, Hsz / 256), 256>>>(embW, target, t, x);

        // q = h @ Wa_w^T + Wa_b  (split-K 16 -> 128 blocks)
        gemm_tn<<<dim3(Hsz / 128, 16, 1), 256>>>(hc, Wa_w, Wa_b, q, Hsz, Hsz, Hsz / 16, 16);

        attn_scores_k<<<dim3(Bsz, Ssz / 8), 256>>>(Uk, q, Va_w, Va_b, sc);
        attn_ctx_k<<<dim3(Bsz, Hsz / 128), 128>>>(sc, enc, x, out_at, t);

        // gi = [emb|ctx] @ W_ih^T + b_ih  (K=2048, split-K 8 -> 192 blocks)
        gemm_tn<<<dim3(H3 / 128, 8, 1), 256>>>(x, W_ih, b_ih, gi, 2 * Hsz, H3, (2 * Hsz) / 8, 8);
        // gh = h @ W_hh^T + b_hh  (K=1024, split-K 8 -> 192 blocks)
        gemm_tn<<<dim3(H3 / 128, 8, 1), 256>>>(hc, W_hh, b_hh, gh, Hsz, H3, Hsz / 8, 8);

        gates_k<<<(Bsz * Hsz) / 256, 256>>>(gi, gh, hc, hn);

        // logits[b, t, :] = h_new @ out_W^T + out_b  (N=32000 -> 250 blocks)
        gemm_tn<<<dim3(Vsz / 128, 1, 1), 256>>>(
            hn, out_W, out_b, out_lp + (size_t)t * Vsz, Hsz, Tsz * Vsz, Hsz, 1);
    }

    // hT (final h is in h0 after the t=9 write)
    copy_k<<<(Bsz * Hsz + 255) / 256, 256>>>(h0, out_h, Bsz * Hsz);
    // in-place log_softmax over V for all B*T rows
    lsm_k<<<Bsz * Tsz, 256>>>(out_lp);
}

// round 2
// speedup vs baseline: 2.5059x; 2.5059x over previous
#include <cuda_runtime.h>
#include <math.h>
#include <stdint.h>

#define Bsz 64
#define Ssz 128
#define Hsz 1024
#define Vsz 32000
#define Tsz 10
#define H3  (3*Hsz)

// ---------------- device scratch (no allocations allowed) ----------------
__device__ float g_Uk[Bsz*Ssz*Hsz];   // 33.5 MB
__device__ float g_h [2*Bsz*Hsz];     // ping-pong hidden
__device__ float g_q [Bsz*Hsz];
__device__ float g_x [Bsz*2*Hsz];     // [emb | ctx]
__device__ float g_gi[Bsz*H3];
__device__ float g_gh[Bsz*H3];
__device__ float g_sc[Bsz*Ssz];

// ---------------- tf32 helpers ----------------
__device__ __forceinline__ float to_tf32(float x) {
    uint32_t u;
    asm("cvt.rna.tf32.f32 %0, %1;" : "=r"(u) : "f"(x));
    return __uint_as_float(u);
}

__device__ __forceinline__ void mma_tf32(float c[4],
                                         uint32_t a0, uint32_t a1, uint32_t a2, uint32_t a3,
                                         uint32_t b0, uint32_t b1)
{
    asm volatile(
        "mma.sync.aligned.m16n8k8.row.col.f32.tf32.tf32.f32 "
        "{%0,%1,%2,%3}, {%4,%5,%6,%7}, {%8,%9}, {%0,%1,%2,%3};"
        : "+f"(c[0]), "+f"(c[1]), "+f"(c[2]), "+f"(c[3])
        : "r"(a0), "r"(a1), "r"(a2), "r"(a3), "r"(b0), "r"(b1));
}

// ---------------- GEMM (tf32 tensor-core): C[M,N] (+)= A[M,K] @ W[N,K]^T (+bias) --------
// block tile 64(M) x 128(N), 256 threads = 8 warps (4M x 2N), warp tile 16x64.
// K staged 32 per iter. grid = (N/128, nSplits, M/64).
// nSplits>1: C pre-zeroed, atomicAdd, bias added by blockIdx.y==0 only.
__global__ __launch_bounds__(256)
void gemm_mma(const float* __restrict__ A, const float* __restrict__ W,
              const float* __restrict__ bias, float* __restrict__ C,
              int K, int ldc, int kPerSplit, int nSplits)
{
    __shared__ __align__(16) float As[64][36];
    __shared__ __align__(16) float Bs[128][36];

    const int t    = threadIdx.x;
    const int lane = t & 31;
    const int wid  = t >> 5;
    const int wm16 = (wid & 3) * 16;   // warp M offset
    const int wn64 = (wid >> 2) * 64;  // warp N offset
    const int m0   = blockIdx.z * 64;
    const int n0   = blockIdx.x * 128;
    const int kb0  = blockIdx.y * kPerSplit;

    const int r  = lane >> 2;   // 0..7
    const int c  = lane & 3;    // 0..3

    float acc[8][4];
    #pragma unroll
    for (int i = 0; i < 8; i++)
        #pragma unroll
        for (int j = 0; j < 4; j++) acc[i][j] = 0.f;

    for (int kb = kb0; kb < kb0 + kPerSplit; kb += 32) {
        __syncthreads();
        // stage A: 64 x 32 floats = 512 float4, 2 per thread
        #pragma unroll
        for (int rr = 0; rr < 2; rr++) {
            int idx = rr * 256 + t;
            int m = idx >> 3, kq = idx & 7;
            float4 v = *(const float4*)(A + (size_t)(m0 + m) * K + kb + (kq << 2));
            v.x = to_tf32(v.x); v.y = to_tf32(v.y);
            v.z = to_tf32(v.z); v.w = to_tf32(v.w);
            *(float4*)(&As[m][kq << 2]) = v;
        }
        // stage B: 128 x 32 floats = 1024 float4, 4 per thread
        #pragma unroll
        for (int rr = 0; rr < 4; rr++) {
            int idx = rr * 256 + t;
            int n = idx >> 3, kq = idx & 7;
            float4 v = *(const float4*)(W + (size_t)(n0 + n) * K + kb + (kq << 2));
            v.x = to_tf32(v.x); v.y = to_tf32(v.y);
            v.z = to_tf32(v.z); v.w = to_tf32(v.w);
            *(float4*)(&Bs[n][kq << 2]) = v;
        }
        __syncthreads();

        #pragma unroll
        for (int kc = 0; kc < 4; kc++) {
            const int k8 = kc << 3;
            uint32_t a0 = __float_as_uint(As[wm16 + r    ][k8 + c    ]);
            uint32_t a1 = __float_as_uint(As[wm16 + r + 8][k8 + c    ]);
            uint32_t a2 = __float_as_uint(As[wm16 + r    ][k8 + c + 4]);
            uint32_t a3 = __float_as_uint(As[wm16 + r + 8][k8 + c + 4]);
            #pragma unroll
            for (int nt = 0; nt < 8; nt++) {
                uint32_t b0 = __float_as_uint(Bs[wn64 + (nt << 3) + r][k8 + c    ]);
                uint32_t b1 = __float_as_uint(Bs[wn64 + (nt << 3) + r][k8 + c + 4]);
                mma_tf32(acc[nt], a0, a1, a2, a3, b0, b1);
            }
        }
    }

    // epilogue: c0:(r, 2c) c1:(r, 2c+1) c2:(r+8, 2c) c3:(r+8, 2c+1)
    const int c2 = c << 1;
    #pragma unroll
    for (int nt = 0; nt < 8; nt++) {
        const int n = n0 + wn64 + (nt << 3) + c2;
        const int m = m0 + wm16 + r;
        if (nSplits == 1) {
            float b0 = bias ? bias[n]     : 0.f;
            float b1 = bias ? bias[n + 1] : 0.f;
            C[(size_t)m * ldc + n]           = acc[nt][0] + b0;
            C[(size_t)m * ldc + n + 1]       = acc[nt][1] + b1;
            C[(size_t)(m + 8) * ldc + n]     = acc[nt][2] + b0;
            C[(size_t)(m + 8) * ldc + n + 1] = acc[nt][3] + b1;
        } else {
            float b0 = (blockIdx.y == 0 && bias) ? bias[n]     : 0.f;
            float b1 = (blockIdx.y == 0 && bias) ? bias[n + 1] : 0.f;
            atomicAdd(&C[(size_t)m * ldc + n],           acc[nt][0] + b0);
            atomicAdd(&C[(size_t)m * ldc + n + 1],       acc[nt][1] + b1);
            atomicAdd(&C[(size_t)(m + 8) * ldc + n],     acc[nt][2] + b0);
            atomicAdd(&C[(size_t)(m + 8) * ldc + n + 1], acc[nt][3] + b1);
        }
    }
}

// ---------------- helpers ----------------
__global__ void copy_k(const float* __restrict__ src, float* __restrict__ dst, int n)
{
    int i = blockIdx.x * blockDim.x + threadIdx.x;
    if (i < n) dst[i] = src[i];
}

__global__ void zero3_k(float* __restrict__ q, float* __restrict__ gi, float* __restrict__ gh)
{
    int i = blockIdx.x * blockDim.x + threadIdx.x;   // grid sized to Bsz*H3 exactly
    if (i < Bsz * Hsz) q[i] = 0.f;
    gi[i] = 0.f;
    gh[i] = 0.f;
}

__global__ void emb_k(const float* __restrict__ embW, const int* __restrict__ target,
                      int t, float* __restrict__ x)
{
    int b = blockIdx.x;
    int h = blockIdx.y * 256 + threadIdx.x;
    int tok = (t == 0) ? 0 : target[b * Tsz + (t - 1)];
    x[b * 2 * Hsz + h] = embW[(size_t)tok * Hsz + h];
}

// scores[b,s] = Va . tanh(q[b] + Uk[b,s]) + Va_b   (one warp per (b,s))
__global__ __launch_bounds__(256)
void attn_scores_k(const float* __restrict__ Uk, const float* __restrict__ q,
                   const float* __restrict__ Va, const float* __restrict__ Vab,
                   float* __restrict__ scores)
{
    int b = blockIdx.x;
    int s = blockIdx.y * 8 + (threadIdx.x >> 5);
    int lane = threadIdx.x & 31;
    const float* ukr = Uk + ((size_t)b * Ssz + s) * Hsz;
    const float* qr  = q + b * Hsz;
    float acc = 0.f;
    for (int h = lane * 4; h < Hsz; h += 128) {
        float4 u  = *(const float4*)(ukr + h);
        float4 qv = *(const float4*)(qr + h);
        float4 vv = *(const float4*)(Va + h);
        acc += vv.x * tanhf(qv.x + u.x);
        acc += vv.y * tanhf(qv.y + u.y);
        acc += vv.z * tanhf(qv.z + u.z);
        acc += vv.w * tanhf(qv.w + u.w);
    }
    #pragma unroll
    for (int o = 16; o; o >>= 1) acc += __shfl_xor_sync(0xffffffffu, acc, o);
    if (!lane) scores[b * Ssz + s] = acc + Vab[0];
}

// softmax over S, write attns slice, ctx[b,h] = sum_s w*E[b,s,h];  grid (B, H/128)
__global__ __launch_bounds__(128)
void attn_ctx_k(const float* __restrict__ sc, const float* __restrict__ E,
                float* __restrict__ x, float* __restrict__ attns, int t)
{
    __shared__ float wsm[Ssz];
    __shared__ float red[4];
    int b = blockIdx.x, tid = threadIdx.x;

    float v0 = sc[b * Ssz + tid];
    float m = v0;
    #pragma unroll
    for (int o = 16; o; o >>= 1) m = fmaxf(m, __shfl_xor_sync(0xffffffffu, m, o));
    if ((tid & 31) == 0) red[tid >> 5] = m;
    __syncthreads();
    float mx = fmaxf(fmaxf(red[0], red[1]), fmaxf(red[2], red[3]));
    __syncthreads();

    float e = expf(v0 - mx);
    float sm = e;
    #pragma unroll
    for (int o = 16; o; o >>= 1) sm += __shfl_xor_sync(0xffffffffu, sm, o);
    if ((tid & 31) == 0) red[tid >> 5] = sm;
    __syncthreads();
    float ssum = red[0] + red[1] + red[2] + red[3];

    float w = e / ssum;
    wsm[tid] = w;
    if (blockIdx.y == 0) attns[((size_t)b * Tsz + t) * Ssz + tid] = w;
    __syncthreads();

    int h = blockIdx.y * 128 + tid;
    const float* Eb = E + (size_t)b * Ssz * Hsz + h;
    float acc = 0.f;
    #pragma unroll 8
    for (int s2 = 0; s2 < Ssz; s2++) acc = fmaf(wsm[s2], Eb[(size_t)s2 * Hsz], acc);
    x[b * 2 * Hsz + Hsz + h] = acc;
}

__global__ void gates_k(const float* __restrict__ gi, const float* __restrict__ gh,
                        const float* __restrict__ hin, float* __restrict__ hout)
{
    int idx = blockIdx.x * blockDim.x + threadIdx.x;   // B*H
    int b = idx >> 10, j = idx & 1023;
    const float* gib = gi + b * H3;
    const float* ghb = gh + b * H3;
    float r = 1.f / (1.f + expf(-(gib[j]           + ghb[j])));
    float z = 1.f / (1.f + expf(-(gib[Hsz + j]     + ghb[Hsz + j])));
    float n = tanhf(gib[2 * Hsz + j] + r * ghb[2 * Hsz + j]);
    hout[idx] = (1.f - z) * n + z * hin[idx];
}

__global__ __launch_bounds__(256)
void lsm_k(float* __restrict__ out)
{
    __shared__ float red[8];
    float* p = out + (size_t)blockIdx.x * Vsz;
    int tid = threadIdx.x;

    float mx = -3.4e38f;
    for (int i = tid; i < Vsz; i += 256) mx = fmaxf(mx, p[i]);
    #pragma unroll
    for (int o = 16; o; o >>= 1) mx = fmaxf(mx, __shfl_xor_sync(0xffffffffu, mx, o));
    if ((tid & 31) == 0) red[tid >> 5] = mx;
    __syncthreads();
    mx = red[0];
    #pragma unroll
    for (int w = 1; w < 8; w++) mx = fmaxf(mx, red[w]);
    __syncthreads();

    float s = 0.f;
    for (int i = tid; i < Vsz; i += 256) s += expf(p[i] - mx);
    #pragma unroll
    for (int o = 16; o; o >>= 1) s += __shfl_xor_sync(0xffffffffu, s, o);
    if ((tid & 31) == 0) red[tid >> 5] = s;
    __syncthreads();
    s = 0.f;
    #pragma unroll
    for (int w = 0; w < 8; w++) s += red[w];
    float lse = mx + logf(s);

    for (int i = tid; i < Vsz; i += 256) p[i] -= lse;
}

// ---------------- launch ----------------
extern "C" void kernel_launch(void* const* d_in, const int* in_sizes, int n_in,
                              void* d_out, int out_size)
{
    const float* enc    = (const float*)d_in[0];
    const float* hidden = (const float*)d_in[1];
    const int*   target = (const int*)  d_in[2];
    const float* embW   = (const float*)d_in[3];
    const float* Wa_w   = (const float*)d_in[4];
    const float* Wa_b   = (const float*)d_in[5];
    const float* Ua_w   = (const float*)d_in[6];
    const float* Ua_b   = (const float*)d_in[7];
    const float* Va_w   = (const float*)d_in[8];
    const float* Va_b   = (const float*)d_in[9];
    const float* W_ih   = (const float*)d_in[10];
    const float* W_hh   = (const float*)d_in[11];
    const float* b_ih   = (const float*)d_in[12];
    const float* b_hh   = (const float*)d_in[13];
    const float* out_W  = (const float*)d_in[14];
    const float* out_b  = (const float*)d_in[15];

    float* out_lp = (float*)d_out;                        // [B,T,V]
    float* out_h  = out_lp + (size_t)Bsz * Tsz * Vsz;     // [1,B,H]
    float* out_at = out_h + (size_t)Bsz * Hsz;            // [B,T,S]

    float *Uk, *hb, *q, *x, *gi, *gh, *sc;
    cudaGetSymbolAddress((void**)&Uk, g_Uk);
    cudaGetSymbolAddress((void**)&hb, g_h);
    cudaGetSymbolAddress((void**)&q,  g_q);
    cudaGetSymbolAddress((void**)&x,  g_x);
    cudaGetSymbolAddress((void**)&gi, g_gi);
    cudaGetSymbolAddress((void**)&gh, g_gh);
    cudaGetSymbolAddress((void**)&sc, g_sc);
    float* h0 = hb;
    float* h1 = hb + Bsz * Hsz;

    // h <- hidden[0]
    copy_k<<<(Bsz * Hsz + 255) / 256, 256>>>(hidden, h0, Bsz * Hsz);

    // Uk[b,s,g] = E[b,s] . Ua_w[g] + Ua_b[g]   (M=8192, N=1024, K=1024)
    gemm_mma<<<dim3(Hsz / 128, 1, (Bsz * Ssz) / 64), 256>>>(
        enc, Ua_w, Ua_b, Uk, Hsz, Hsz, Hsz, 1);

    for (int t = 0; t < Tsz; t++) {
        float* hc = (t & 1) ? h1 : h0;
        float* hn = (t & 1) ? h0 : h1;

        zero3_k<<<(Bsz * H3) / 256, 256>>>(q, gi, gh);
        emb_k<<<dim3(Bsz, Hsz / 256), 256>>>(embW, target, t, x);

        // q = h @ Wa_w^T + Wa_b  (split-K 16 -> 128 blocks)
        gemm_mma<<<dim3(Hsz / 128, 16, 1), 256>>>(hc, Wa_w, Wa_b, q, Hsz, Hsz, Hsz / 16, 16);

        attn_scores_k<<<dim3(Bsz, Ssz / 8), 256>>>(Uk, q, Va_w, Va_b, sc);
        attn_ctx_k<<<dim3(Bsz, Hsz / 128), 128>>>(sc, enc, x, out_at, t);

        // gi = [emb|ctx] @ W_ih^T + b_ih  (K=2048, split-K 8 -> 192 blocks)
        gemm_mma<<<dim3(H3 / 128, 8, 1), 256>>>(x, W_ih, b_ih, gi, 2 * Hsz, H3, (2 * Hsz) / 8, 8);
        // gh = h @ W_hh^T + b_hh  (K=1024, split-K 8 -> 192 blocks)
        gemm_mma<<<dim3(H3 / 128, 8, 1), 256>>>(hc, W_hh, b_hh, gh, Hsz, H3, Hsz / 8, 8);

        gates_k<<<(Bsz * Hsz) / 256, 256>>>(gi, gh, hc, hn);

        // logits[b, t, :] = h_new @ out_W^T + out_b  (N=32000 -> 250 blocks)
        gemm_mma<<<dim3(Vsz / 128, 1, 1), 256>>>(
            hn, out_W, out_b, out_lp + (size_t)t * Vsz, Hsz, Tsz * Vsz, Hsz, 1);
    }

    // hT (final h is in h0 after the t=9 write)
    copy_k<<<(Bsz * Hsz + 255) / 256, 256>>>(h0, out_h, Bsz * Hsz);
    // in-place log_softmax over V for all B*T rows
    lsm_k<<<Bsz * Tsz, 256>>>(out_lp);
}

// round 3
// speedup vs baseline: 3.1187x; 1.2446x over previous
#include <cuda_runtime.h>
#include <math.h>
#include <stdint.h>

#define Bsz 64
#define Ssz 128
#define Hsz 1024
#define Vsz 32000
#define Tsz 10
#define H3  (3*Hsz)

// ---------------- device scratch (no allocations allowed) ----------------
__device__ float g_Uk  [Bsz*Ssz*Hsz];    // 33.5 MB
__device__ float g_h0  [Bsz*Hsz];        // initial hidden copy
__device__ float g_hist[Tsz*Bsz*Hsz];    // all h_t, feeds batched logits GEMM
__device__ float g_q   [Bsz*Hsz];
__device__ float g_x   [Bsz*2*Hsz];      // [emb | ctx]
__device__ float g_gi  [Bsz*H3];
__device__ float g_gh  [Bsz*H3];
__device__ float g_sc  [Bsz*Ssz];

// ---------------- tf32 helpers ----------------
__device__ __forceinline__ float to_tf32(float x) {
    uint32_t u;
    asm("cvt.rna.tf32.f32 %0, %1;" : "=r"(u) : "f"(x));
    return __uint_as_float(u);
}

__device__ __forceinline__ void mma_tf32(float c[4],
                                         uint32_t a0, uint32_t a1, uint32_t a2, uint32_t a3,
                                         uint32_t b0, uint32_t b1)
{
    asm volatile(
        "mma.sync.aligned.m16n8k8.row.col.f32.tf32.tf32.f32 "
        "{%0,%1,%2,%3}, {%4,%5,%6,%7}, {%8,%9}, {%0,%1,%2,%3};"
        : "+f"(c[0]), "+f"(c[1]), "+f"(c[2]), "+f"(c[3])
        : "r"(a0), "r"(a1), "r"(a2), "r"(a3), "r"(b0), "r"(b1));
}

// ---------------- GEMM (tf32 tensor-core): C[M,N] (+)= A[M,K] @ W[N,K]^T (+bias) --------
// block tile 64(M) x 128(N), 256 threads = 8 warps (4M x 2N), warp tile 16x64.
// grid = (N/128, nSplits, M/64).
// nSplits>1: C pre-zeroed, atomicAdd, bias added by blockIdx.y==0 only.
// permuteTB: row m = t*64+b (M=T*64) -> C row (b*Tsz + t)   [logits epilogue]
__global__ __launch_bounds__(256)
void gemm_mma(const float* __restrict__ A, const float* __restrict__ W,
              const float* __restrict__ bias, float* __restrict__ C,
              int K, int ldc, int kPerSplit, int nSplits, int permuteTB)
{
    __shared__ __align__(16) float As[64][36];
    __shared__ __align__(16) float Bs[128][36];

    const int t    = threadIdx.x;
    const int lane = t & 31;
    const int wid  = t >> 5;
    const int wm16 = (wid & 3) * 16;   // warp M offset
    const int wn64 = (wid >> 2) * 64;  // warp N offset
    const int m0   = blockIdx.z * 64;
    const int n0   = blockIdx.x * 128;
    const int kb0  = blockIdx.y * kPerSplit;

    const int r  = lane >> 2;   // 0..7
    const int c  = lane & 3;    // 0..3

    float acc[8][4];
    #pragma unroll
    for (int i = 0; i < 8; i++)
        #pragma unroll
        for (int j = 0; j < 4; j++) acc[i][j] = 0.f;

    for (int kb = kb0; kb < kb0 + kPerSplit; kb += 32) {
        __syncthreads();
        // stage A: 64 x 32 floats = 512 float4, 2 per thread
        #pragma unroll
        for (int rr = 0; rr < 2; rr++) {
            int idx = rr * 256 + t;
            int m = idx >> 3, kq = idx & 7;
            float4 v = *(const float4*)(A + (size_t)(m0 + m) * K + kb + (kq << 2));
            v.x = to_tf32(v.x); v.y = to_tf32(v.y);
            v.z = to_tf32(v.z); v.w = to_tf32(v.w);
            *(float4*)(&As[m][kq << 2]) = v;
        }
        // stage B: 128 x 32 floats = 1024 float4, 4 per thread
        #pragma unroll
        for (int rr = 0; rr < 4; rr++) {
            int idx = rr * 256 + t;
            int n = idx >> 3, kq = idx & 7;
            float4 v = *(const float4*)(W + (size_t)(n0 + n) * K + kb + (kq << 2));
            v.x = to_tf32(v.x); v.y = to_tf32(v.y);
            v.z = to_tf32(v.z); v.w = to_tf32(v.w);
            *(float4*)(&Bs[n][kq << 2]) = v;
        }
        __syncthreads();

        #pragma unroll
        for (int kc = 0; kc < 4; kc++) {
            const int k8 = kc << 3;
            uint32_t a0 = __float_as_uint(As[wm16 + r    ][k8 + c    ]);
            uint32_t a1 = __float_as_uint(As[wm16 + r + 8][k8 + c    ]);
            uint32_t a2 = __float_as_uint(As[wm16 + r    ][k8 + c + 4]);
            uint32_t a3 = __float_as_uint(As[wm16 + r + 8][k8 + c + 4]);
            #pragma unroll
            for (int nt = 0; nt < 8; nt++) {
                uint32_t b0 = __float_as_uint(Bs[wn64 + (nt << 3) + r][k8 + c    ]);
                uint32_t b1 = __float_as_uint(Bs[wn64 + (nt << 3) + r][k8 + c + 4]);
                mma_tf32(acc[nt], a0, a1, a2, a3, b0, b1);
            }
        }
    }

    // epilogue: c0:(r, 2c) c1:(r, 2c+1) c2:(r+8, 2c) c3:(r+8, 2c+1)
    const int c2 = c << 1;
    #pragma unroll
    for (int nt = 0; nt < 8; nt++) {
        const int n = n0 + wn64 + (nt << 3) + c2;
        int m  = m0 + wm16 + r;       // logical row
        int m2 = m + 8;
        if (permuteTB) {              // m = t*64 + b  ->  row b*Tsz + t
            m  = ((m  & 63) * Tsz) + (m  >> 6);
            m2 = ((m2 & 63) * Tsz) + (m2 >> 6);
        }
        if (nSplits == 1) {
            float b0 = bias ? bias[n]     : 0.f;
            float b1 = bias ? bias[n + 1] : 0.f;
            C[(size_t)m  * ldc + n]     = acc[nt][0] + b0;
            C[(size_t)m  * ldc + n + 1] = acc[nt][1] + b1;
            C[(size_t)m2 * ldc + n]     = acc[nt][2] + b0;
            C[(size_t)m2 * ldc + n + 1] = acc[nt][3] + b1;
        } else {
            float b0 = (blockIdx.y == 0 && bias) ? bias[n]     : 0.f;
            float b1 = (blockIdx.y == 0 && bias) ? bias[n + 1] : 0.f;
            atomicAdd(&C[(size_t)m  * ldc + n],     acc[nt][0] + b0);
            atomicAdd(&C[(size_t)m  * ldc + n + 1], acc[nt][1] + b1);
            atomicAdd(&C[(size_t)m2 * ldc + n],     acc[nt][2] + b0);
            atomicAdd(&C[(size_t)m2 * ldc + n + 1], acc[nt][3] + b1);
        }
    }
}

// ---------------- helpers ----------------
__global__ void copy_k(const float* __restrict__ src, float* __restrict__ dst, int n)
{
    int i = blockIdx.x * blockDim.x + threadIdx.x;
    if (i < n) dst[i] = src[i];
}

// fused: zero q/gi/gh + gather embedding into x[:, 0:H]
__global__ void prep_k(float* __restrict__ q, float* __restrict__ gi, float* __restrict__ gh,
                       const float* __restrict__ embW, const int* __restrict__ target,
                       int t, float* __restrict__ x)
{
    int i = blockIdx.x * blockDim.x + threadIdx.x;   // grid covers Bsz*H3 exactly
    gi[i] = 0.f;
    gh[i] = 0.f;
    if (i < Bsz * Hsz) {
        q[i] = 0.f;
        int b = i >> 10, h = i & 1023;
        int tok = (t == 0) ? 0 : target[b * Tsz + (t - 1)];
        x[b * 2 * Hsz + h] = embW[(size_t)tok * Hsz + h];
    }
}

// scores[b,s] = Va . tanh(q[b] + Uk[b,s]) + Va_b   (one warp per (b,s))
__global__ __launch_bounds__(256)
void attn_scores_k(const float* __restrict__ Uk, const float* __restrict__ q,
                   const float* __restrict__ Va, const float* __restrict__ Vab,
                   float* __restrict__ scores)
{
    int b = blockIdx.x;
    int s = blockIdx.y * 8 + (threadIdx.x >> 5);
    int lane = threadIdx.x & 31;
    const float* ukr = Uk + ((size_t)b * Ssz + s) * Hsz;
    const float* qr  = q + b * Hsz;
    float acc = 0.f;
    for (int h = lane * 4; h < Hsz; h += 128) {
        float4 u  = *(const float4*)(ukr + h);
        float4 qv = *(const float4*)(qr + h);
        float4 vv = *(const float4*)(Va + h);
        acc += vv.x * tanhf(qv.x + u.x);
        acc += vv.y * tanhf(qv.y + u.y);
        acc += vv.z * tanhf(qv.z + u.z);
        acc += vv.w * tanhf(qv.w + u.w);
    }
    #pragma unroll
    for (int o = 16; o; o >>= 1) acc += __shfl_xor_sync(0xffffffffu, acc, o);
    if (!lane) scores[b * Ssz + s] = acc + Vab[0];
}

// softmax over S, write attns slice, ctx[b,h] = sum_s w*E[b,s,h];  grid (B, H/128)
__global__ __launch_bounds__(128)
void attn_ctx_k(const float* __restrict__ sc, const float* __restrict__ E,
                float* __restrict__ x, float* __restrict__ attns, int t)
{
    __shared__ float wsm[Ssz];
    __shared__ float red[4];
    int b = blockIdx.x, tid = threadIdx.x;

    float v0 = sc[b * Ssz + tid];
    float m = v0;
    #pragma unroll
    for (int o = 16; o; o >>= 1) m = fmaxf(m, __shfl_xor_sync(0xffffffffu, m, o));
    if ((tid & 31) == 0) red[tid >> 5] = m;
    __syncthreads();
    float mx = fmaxf(fmaxf(red[0], red[1]), fmaxf(red[2], red[3]));
    __syncthreads();

    float e = expf(v0 - mx);
    float sm = e;
    #pragma unroll
    for (int o = 16; o; o >>= 1) sm += __shfl_xor_sync(0xffffffffu, sm, o);
    if ((tid & 31) == 0) red[tid >> 5] = sm;
    __syncthreads();
    float ssum = red[0] + red[1] + red[2] + red[3];

    float w = e / ssum;
    wsm[tid] = w;
    if (blockIdx.y == 0) attns[((size_t)b * Tsz + t) * Ssz + tid] = w;
    __syncthreads();

    int h = blockIdx.y * 128 + tid;
    const float* Eb = E + (size_t)b * Ssz * Hsz + h;
    float acc = 0.f;
    #pragma unroll 8
    for (int s2 = 0; s2 < Ssz; s2++) acc = fmaf(wsm[s2], Eb[(size_t)s2 * Hsz], acc);
    x[b * 2 * Hsz + Hsz + h] = acc;
}

__global__ void gates_k(const float* __restrict__ gi, const float* __restrict__ gh,
                        const float* __restrict__ hin, float* __restrict__ hout)
{
    int idx = blockIdx.x * blockDim.x + threadIdx.x;   // B*H
    int b = idx >> 10, j = idx & 1023;
    const float* gib = gi + b * H3;
    const float* ghb = gh + b * H3;
    float r = 1.f / (1.f + expf(-(gib[j]           + ghb[j])));
    float z = 1.f / (1.f + expf(-(gib[Hsz + j]     + ghb[Hsz + j])));
    float n = tanhf(gib[2 * Hsz + j] + r * ghb[2 * Hsz + j]);
    hout[idx] = (1.f - z) * n + z * hin[idx];
}

__global__ __launch_bounds__(256)
void lsm_k(float* __restrict__ out)
{
    __shared__ float red[8];
    float* p = out + (size_t)blockIdx.x * Vsz;
    int tid = threadIdx.x;

    float mx = -3.4e38f;
    for (int i = tid; i < Vsz; i += 256) mx = fmaxf(mx, p[i]);
    #pragma unroll
    for (int o = 16; o; o >>= 1) mx = fmaxf(mx, __shfl_xor_sync(0xffffffffu, mx, o));
    if ((tid & 31) == 0) red[tid >> 5] = mx;
    __syncthreads();
    mx = red[0];
    #pragma unroll
    for (int w = 1; w < 8; w++) mx = fmaxf(mx, red[w]);
    __syncthreads();

    float s = 0.f;
    for (int i = tid; i < Vsz; i += 256) s += expf(p[i] - mx);
    #pragma unroll
    for (int o = 16; o; o >>= 1) s += __shfl_xor_sync(0xffffffffu, s, o);
    if ((tid & 31) == 0) red[tid >> 5] = s;
    __syncthreads();
    s = 0.f;
    #pragma unroll
    for (int w = 0; w < 8; w++) s += red[w];
    float lse = mx + logf(s);

    for (int i = tid; i < Vsz; i += 256) p[i] -= lse;
}

// ---------------- launch ----------------
extern "C" void kernel_launch(void* const* d_in, const int* in_sizes, int n_in,
                              void* d_out, int out_size)
{
    const float* enc    = (const float*)d_in[0];
    const float* hidden = (const float*)d_in[1];
    const int*   target = (const int*)  d_in[2];
    const float* embW   = (const float*)d_in[3];
    const float* Wa_w   = (const float*)d_in[4];
    const float* Wa_b   = (const float*)d_in[5];
    const float* Ua_w   = (const float*)d_in[6];
    const float* Ua_b   = (const float*)d_in[7];
    const float* Va_w   = (const float*)d_in[8];
    const float* Va_b   = (const float*)d_in[9];
    const float* W_ih   = (const float*)d_in[10];
    const float* W_hh   = (const float*)d_in[11];
    const float* b_ih   = (const float*)d_in[12];
    const float* b_hh   = (const float*)d_in[13];
    const float* out_W  = (const float*)d_in[14];
    const float* out_b  = (const float*)d_in[15];

    float* out_lp = (float*)d_out;                        // [B,T,V]
    float* out_h  = out_lp + (size_t)Bsz * Tsz * Vsz;     // [1,B,H]
    float* out_at = out_h + (size_t)Bsz * Hsz;            // [B,T,S]

    float *Uk, *h0, *hist, *q, *x, *gi, *gh, *sc;
    cudaGetSymbolAddress((void**)&Uk,   g_Uk);
    cudaGetSymbolAddress((void**)&h0,   g_h0);
    cudaGetSymbolAddress((void**)&hist, g_hist);
    cudaGetSymbolAddress((void**)&q,    g_q);
    cudaGetSymbolAddress((void**)&x,    g_x);
    cudaGetSymbolAddress((void**)&gi,   g_gi);
    cudaGetSymbolAddress((void**)&gh,   g_gh);
    cudaGetSymbolAddress((void**)&sc,   g_sc);

    // h <- hidden[0]
    copy_k<<<(Bsz * Hsz + 255) / 256, 256>>>(hidden, h0, Bsz * Hsz);

    // Uk[b,s,g] = E[b,s] . Ua_w[g] + Ua_b[g]   (M=8192, N=1024, K=1024)
    gemm_mma<<<dim3(Hsz / 128, 1, (Bsz * Ssz) / 64), 256>>>(
        enc, Ua_w, Ua_b, Uk, Hsz, Hsz, Hsz, 1, 0);

    for (int t = 0; t < Tsz; t++) {
        const float* hc = (t == 0) ? h0 : hist + (size_t)(t - 1) * Bsz * Hsz;
        float* hn = hist + (size_t)t * Bsz * Hsz;

        prep_k<<<(Bsz * H3) / 256, 256>>>(q, gi, gh, embW, target, t, x);

        // q = h @ Wa_w^T + Wa_b  (split-K 16 -> 128 blocks)
        gemm_mma<<<dim3(Hsz / 128, 16, 1), 256>>>(hc, Wa_w, Wa_b, q, Hsz, Hsz, Hsz / 16, 16, 0);

        attn_scores_k<<<dim3(Bsz, Ssz / 8), 256>>>(Uk, q, Va_w, Va_b, sc);
        attn_ctx_k<<<dim3(Bsz, Hsz / 128), 128>>>(sc, enc, x, out_at, t);

        // gi = [emb|ctx] @ W_ih^T + b_ih  (K=2048, split-K 8 -> 192 blocks)
        gemm_mma<<<dim3(H3 / 128, 8, 1), 256>>>(x, W_ih, b_ih, gi, 2 * Hsz, H3, (2 * Hsz) / 8, 8, 0);
        // gh = h @ W_hh^T + b_hh  (K=1024, split-K 8 -> 192 blocks)
        gemm_mma<<<dim3(H3 / 128, 8, 1), 256>>>(hc, W_hh, b_hh, gh, Hsz, H3, Hsz / 8, 8, 0);

        gates_k<<<(Bsz * Hsz) / 256, 256>>>(gi, gh, hc, hn);
    }

    // batched logits: M = T*B = 640 rows (hist), N = 32000, out_W read ONCE.
    // epilogue permutes row t*64+b -> out row b*Tsz+t.
    gemm_mma<<<dim3(Vsz / 128, 1, Tsz), 256>>>(
        hist, out_W, out_b, out_lp, Hsz, Vsz, Hsz, 1, 1);

    // hT = hist[T-1]
    copy_k<<<(Bsz * Hsz + 255) / 256, 256>>>(hist + (size_t)(Tsz - 1) * Bsz * Hsz,
                                             out_h, Bsz * Hsz);
    // in-place log_softmax over V for all B*T rows
    lsm_k<<<Bsz * Tsz, 256>>>(out_lp);
}

// round 4
// speedup vs baseline: 3.3565x; 1.0762x over previous
#include <cuda_runtime.h>
#include <math.h>
#include <stdint.h>

#define Bsz 64
#define Ssz 128
#define Hsz 1024
#define Vsz 32000
#define Tsz 10
#define H3  (3*Hsz)
#define QSPL 16
#define GSPL 8

// ---------------- device scratch ----------------
__device__ float g_Uk  [Bsz*Ssz*Hsz];          // 33.5 MB
__device__ float g_h0  [Bsz*Hsz];
__device__ float g_hist[Tsz*Bsz*Hsz];          // all h_t
__device__ float g_xall[Tsz*Bsz*2*Hsz];        // per-step [emb | ctx]
__device__ float g_qp  [QSPL*Bsz*Hsz];         // q split-K partials
__device__ float g_gip [GSPL*Bsz*H3];          // gi partials
__device__ float g_ghp [GSPL*Bsz*H3];          // gh partials

// ---------------- tf32 helpers ----------------
__device__ __forceinline__ float to_tf32(float x) {
    uint32_t u;
    asm("cvt.rna.tf32.f32 %0, %1;" : "=r"(u) : "f"(x));
    return __uint_as_float(u);
}

__device__ __forceinline__ void mma_tf32(float c[4],
                                         uint32_t a0, uint32_t a1, uint32_t a2, uint32_t a3,
                                         uint32_t b0, uint32_t b1)
{
    asm volatile(
        "mma.sync.aligned.m16n8k8.row.col.f32.tf32.tf32.f32 "
        "{%0,%1,%2,%3}, {%4,%5,%6,%7}, {%8,%9}, {%0,%1,%2,%3};"
        : "+f"(c[0]), "+f"(c[1]), "+f"(c[2]), "+f"(c[3])
        : "r"(a0), "r"(a1), "r"(a2), "r"(a3), "r"(b0), "r"(b1));
}

// ======== BIG GEMM: 128Mx128N tile, 8 warps (4M x 2N), warp 32x64 ========
// C[M,N] = A[M,K] @ W[N,K]^T + bias.  grid (N/128, 1, M/128).
// permuteTB: logical row m = t*64+b -> C row b*Tsz+t.
__global__ __launch_bounds__(256)
void gemm_big(const float* __restrict__ A, const float* __restrict__ W,
              const float* __restrict__ bias, float* __restrict__ C,
              int K, int ldc, int permuteTB)
{
    __shared__ __align__(16) float As[128][36];
    __shared__ __align__(16) float Bs[128][36];

    const int t    = threadIdx.x;
    const int lane = t & 31;
    const int wid  = t >> 5;
    const int wm32 = (wid & 3) * 32;
    const int wn64 = (wid >> 2) * 64;
    const int m0   = blockIdx.z * 128;
    const int n0   = blockIdx.x * 128;
    const int r    = lane >> 2;
    const int c    = lane & 3;

    float acc[2][8][4];
    #pragma unroll
    for (int mi = 0; mi < 2; mi++)
        #pragma unroll
        for (int nt = 0; nt < 8; nt++)
            #pragma unroll
            for (int j = 0; j < 4; j++) acc[mi][nt][j] = 0.f;

    for (int kb = 0; kb < K; kb += 32) {
        __syncthreads();
        #pragma unroll
        for (int rr = 0; rr < 4; rr++) {
            int idx = rr * 256 + t;
            int m = idx >> 3, kq = idx & 7;
            float4 v = *(const float4*)(A + (size_t)(m0 + m) * K + kb + (kq << 2));
            v.x = to_tf32(v.x); v.y = to_tf32(v.y);
            v.z = to_tf32(v.z); v.w = to_tf32(v.w);
            *(float4*)(&As[m][kq << 2]) = v;
        }
        #pragma unroll
        for (int rr = 0; rr < 4; rr++) {
            int idx = rr * 256 + t;
            int n = idx >> 3, kq = idx & 7;
            float4 v = *(const float4*)(W + (size_t)(n0 + n) * K + kb + (kq << 2));
            v.x = to_tf32(v.x); v.y = to_tf32(v.y);
            v.z = to_tf32(v.z); v.w = to_tf32(v.w);
            *(float4*)(&Bs[n][kq << 2]) = v;
        }
        __syncthreads();

        #pragma unroll
        for (int kc = 0; kc < 4; kc++) {
            const int k8 = kc << 3;
            uint32_t a[2][4];
            #pragma unroll
            for (int mi = 0; mi < 2; mi++) {
                const int mr = wm32 + (mi << 4) + r;
                a[mi][0] = __float_as_uint(As[mr    ][k8 + c    ]);
                a[mi][1] = __float_as_uint(As[mr + 8][k8 + c    ]);
                a[mi][2] = __float_as_uint(As[mr    ][k8 + c + 4]);
                a[mi][3] = __float_as_uint(As[mr + 8][k8 + c + 4]);
            }
            #pragma unroll
            for (int nt = 0; nt < 8; nt++) {
                uint32_t b0 = __float_as_uint(Bs[wn64 + (nt << 3) + r][k8 + c    ]);
                uint32_t b1 = __float_as_uint(Bs[wn64 + (nt << 3) + r][k8 + c + 4]);
                mma_tf32(acc[0][nt], a[0][0], a[0][1], a[0][2], a[0][3], b0, b1);
                mma_tf32(acc[1][nt], a[1][0], a[1][1], a[1][2], a[1][3], b0, b1);
            }
        }
    }

    const int c2 = c << 1;
    #pragma unroll
    for (int mi = 0; mi < 2; mi++) {
        int mlog  = m0 + wm32 + (mi << 4) + r;
        int mlog2 = mlog + 8;
        int m  = permuteTB ? ((mlog  & 63) * Tsz + (mlog  >> 6)) : mlog;
        int m2 = permuteTB ? ((mlog2 & 63) * Tsz + (mlog2 >> 6)) : mlog2;
        #pragma unroll
        for (int nt = 0; nt < 8; nt++) {
            const int n = n0 + wn64 + (nt << 3) + c2;
            float b0 = bias[n], b1 = bias[n + 1];
            float2 v0 = make_float2(acc[mi][nt][0] + b0, acc[mi][nt][1] + b1);
            float2 v1 = make_float2(acc[mi][nt][2] + b0, acc[mi][nt][3] + b1);
            *(float2*)(C + (size_t)m  * ldc + n) = v0;
            *(float2*)(C + (size_t)m2 * ldc + n) = v1;
        }
    }
}

// ======== SMALL GEMM core: 64Mx128N tile (M=64), partial store, no bias ========
__device__ __forceinline__ void small_core(
    const float* __restrict__ A, const float* __restrict__ W, float* __restrict__ Cp,
    int K, int N, int kb0, int kPerSplit, int n0,
    float (*As)[36], float (*Bs)[36])
{
    const int t    = threadIdx.x;
    const int lane = t & 31;
    const int wid  = t >> 5;
    const int wm16 = (wid & 3) * 16;
    const int wn64 = (wid >> 2) * 64;
    const int r    = lane >> 2;
    const int c    = lane & 3;

    float acc[8][4];
    #pragma unroll
    for (int i = 0; i < 8; i++)
        #pragma unroll
        for (int j = 0; j < 4; j++) acc[i][j] = 0.f;

    for (int kb = kb0; kb < kb0 + kPerSplit; kb += 32) {
        __syncthreads();
        #pragma unroll
        for (int rr = 0; rr < 2; rr++) {
            int idx = rr * 256 + t;
            int m = idx >> 3, kq = idx & 7;
            float4 v = *(const float4*)(A + (size_t)m * K + kb + (kq << 2));
            v.x = to_tf32(v.x); v.y = to_tf32(v.y);
            v.z = to_tf32(v.z); v.w = to_tf32(v.w);
            *(float4*)(&As[m][kq << 2]) = v;
        }
        #pragma unroll
        for (int rr = 0; rr < 4; rr++) {
            int idx = rr * 256 + t;
            int n = idx >> 3, kq = idx & 7;
            float4 v = *(const float4*)(W + (size_t)(n0 + n) * K + kb + (kq << 2));
            v.x = to_tf32(v.x); v.y = to_tf32(v.y);
            v.z = to_tf32(v.z); v.w = to_tf32(v.w);
            *(float4*)(&Bs[n][kq << 2]) = v;
        }
        __syncthreads();

        #pragma unroll
        for (int kc = 0; kc < 4; kc++) {
            const int k8 = kc << 3;
            uint32_t a0 = __float_as_uint(As[wm16 + r    ][k8 + c    ]);
            uint32_t a1 = __float_as_uint(As[wm16 + r + 8][k8 + c    ]);
            uint32_t a2 = __float_as_uint(As[wm16 + r    ][k8 + c + 4]);
            uint32_t a3 = __float_as_uint(As[wm16 + r + 8][k8 + c + 4]);
            #pragma unroll
            for (int nt = 0; nt < 8; nt++) {
                uint32_t b0 = __float_as_uint(Bs[wn64 + (nt << 3) + r][k8 + c    ]);
                uint32_t b1 = __float_as_uint(Bs[wn64 + (nt << 3) + r][k8 + c + 4]);
                mma_tf32(acc[nt], a0, a1, a2, a3, b0, b1);
            }
        }
    }

    const int c2 = c << 1;
    #pragma unroll
    for (int nt = 0; nt < 8; nt++) {
        const int n = n0 + wn64 + (nt << 3) + c2;
        const int m = wm16 + r;
        *(float2*)(Cp + (size_t)m       * N + n) = make_float2(acc[nt][0], acc[nt][1]);
        *(float2*)(Cp + (size_t)(m + 8) * N + n) = make_float2(acc[nt][2], acc[nt][3]);
    }
}

// q partials: grid (Hsz/128, QSPL).  qP[split][64][1024]
__global__ __launch_bounds__(256)
void gemm_q_k(const float* __restrict__ h, const float* __restrict__ Wa_w,
              float* __restrict__ qP)
{
    __shared__ __align__(16) float As[64][36];
    __shared__ __align__(16) float Bs[128][36];
    const int spl = blockIdx.y;
    const int kps = Hsz / QSPL;  // 64
    small_core(h, Wa_w, qP + (size_t)spl * Bsz * Hsz,
               Hsz, Hsz, spl * kps, kps, blockIdx.x * 128, As, Bs);
}

// gi/gh partials: grid (H3/128, GSPL, 2). z=0: gi (A=x_t,K=2048), z=1: gh (A=h,K=1024)
__global__ __launch_bounds__(256)
void gemm_gru_k(const float* __restrict__ x_t, const float* __restrict__ h,
                const float* __restrict__ W_ih, const float* __restrict__ W_hh,
                float* __restrict__ giP, float* __restrict__ ghP)
{
    __shared__ __align__(16) float As[64][36];
    __shared__ __align__(16) float Bs[128][36];
    const int spl = blockIdx.y;
    const int z = blockIdx.z;
    const float* A = z ? h : x_t;
    const float* W = z ? W_hh : W_ih;
    float* Cp = (z ? ghP : giP) + (size_t)spl * Bsz * H3;
    const int K = z ? Hsz : 2 * Hsz;
    const int kps = K / GSPL;
    small_core(A, W, Cp, K, H3, spl * kps, kps, blockIdx.x * 128, As, Bs);
}

// ======== fused attention: q-reduce + scores + softmax + ctx + attns ========
__global__ __launch_bounds__(1024)
void attn_all_k(const float* __restrict__ qP, const float* __restrict__ Wa_b,
                const float* __restrict__ Uk, const float* __restrict__ Va,
                const float* __restrict__ Vab, const float* __restrict__ enc,
                float* __restrict__ x_t, float* __restrict__ attns, int t)
{
    __shared__ __align__(16) float qs[Hsz];
    __shared__ float sv[Ssz];
    const int b = blockIdx.x, tid = threadIdx.x;
    const int w = tid >> 5, lane = tid & 31;

    // reduce q split-K partials into smem (+bias)
    float qacc = Wa_b[tid];
    #pragma unroll
    for (int p = 0; p < QSPL; p++) qacc += qP[(size_t)p * Bsz * Hsz + b * Hsz + tid];
    qs[tid] = qacc;
    __syncthreads();

    // scores: warp w handles s = w, w+32, w+64, w+96
    #pragma unroll
    for (int si = 0; si < 4; si++) {
        const int s = (si << 5) + w;
        const float* ukr = Uk + ((size_t)b * Ssz + s) * Hsz;
        float a = 0.f;
        #pragma unroll
        for (int j = 0; j < 8; j++) {
            const int hh = lane * 4 + j * 128;
            float4 u  = *(const float4*)(ukr + hh);
            float4 qv = *(const float4*)(&qs[hh]);
            float4 vv = *(const float4*)(Va + hh);
            a += vv.x * tanhf(qv.x + u.x);
            a += vv.y * tanhf(qv.y + u.y);
            a += vv.z * tanhf(qv.z + u.z);
            a += vv.w * tanhf(qv.w + u.w);
        }
        #pragma unroll
        for (int o = 16; o; o >>= 1) a += __shfl_xor_sync(0xffffffffu, a, o);
        if (!lane) sv[s] = a + Vab[0];
    }
    __syncthreads();

    // softmax over 128 (warp 0, 4 per lane) + attns write
    if (w == 0) {
        float v0 = sv[lane], v1 = sv[lane + 32], v2 = sv[lane + 64], v3 = sv[lane + 96];
        float mx = fmaxf(fmaxf(v0, v1), fmaxf(v2, v3));
        #pragma unroll
        for (int o = 16; o; o >>= 1) mx = fmaxf(mx, __shfl_xor_sync(0xffffffffu, mx, o));
        float e0 = expf(v0 - mx), e1 = expf(v1 - mx), e2 = expf(v2 - mx), e3 = expf(v3 - mx);
        float sm = e0 + e1 + e2 + e3;
        #pragma unroll
        for (int o = 16; o; o >>= 1) sm += __shfl_xor_sync(0xffffffffu, sm, o);
        float inv = 1.f / sm;
        float w0 = e0 * inv, w1 = e1 * inv, w2 = e2 * inv, w3 = e3 * inv;
        sv[lane] = w0; sv[lane + 32] = w1; sv[lane + 64] = w2; sv[lane + 96] = w3;
        float* ar = attns + ((size_t)b * Tsz + t) * Ssz;
        ar[lane] = w0; ar[lane + 32] = w1; ar[lane + 64] = w2; ar[lane + 96] = w3;
    }
    __syncthreads();

    // ctx[h=tid] = sum_s w[s] * E[b,s,tid]
    const float* Eb = enc + (size_t)b * Ssz * Hsz + tid;
    float cacc = 0.f;
    #pragma unroll 8
    for (int s = 0; s < Ssz; s++) cacc = fmaf(sv[s], Eb[(size_t)s * Hsz], cacc);
    x_t[b * 2 * Hsz + Hsz + tid] = cacc;
}

// ======== GRU gates: reduce partials + nonlinearity ========
__global__ void gates_k(const float* __restrict__ giP, const float* __restrict__ ghP,
                        const float* __restrict__ b_ih, const float* __restrict__ b_hh,
                        const float* __restrict__ hin, float* __restrict__ hout)
{
    const int idx = blockIdx.x * 256 + threadIdx.x;  // B*H
    const int b = idx >> 10, j = idx & 1023;
    float gir = b_ih[j], giz = b_ih[Hsz + j], gin = b_ih[2 * Hsz + j];
    float ghr = b_hh[j], ghz = b_hh[Hsz + j], ghn = b_hh[2 * Hsz + j];
    const int base = b * H3 + j;
    #pragma unroll
    for (int p = 0; p < GSPL; p++) {
        const float* gp = giP + (size_t)p * Bsz * H3 + base;
        gir += gp[0]; giz += gp[Hsz]; gin += gp[2 * Hsz];
        const float* hp = ghP + (size_t)p * Bsz * H3 + base;
        ghr += hp[0]; ghz += hp[Hsz]; ghn += hp[2 * Hsz];
    }
    float r = 1.f / (1.f + expf(-(gir + ghr)));
    float z = 1.f / (1.f + expf(-(giz + ghz)));
    float n = tanhf(gin + r * ghn);
    hout[idx] = (1.f - z) * n + z * hin[idx];
}

// ======== init: h0 copy + all embedding gathers ========
__global__ void init_k(const float* __restrict__ hidden, float* __restrict__ h0,
                       const float* __restrict__ embW, const int* __restrict__ target,
                       float* __restrict__ xall)
{
    const int idx = blockIdx.x * 256 + threadIdx.x;   // T*B*H
    const int t = idx / (Bsz * Hsz);
    const int rem = idx - t * (Bsz * Hsz);
    const int b = rem >> 10, h = rem & 1023;
    const int tok = (t == 0) ? 0 : target[b * Tsz + (t - 1)];
    xall[(size_t)t * Bsz * 2 * Hsz + b * 2 * Hsz + h] = embW[(size_t)tok * Hsz + h];
    if (idx < Bsz * Hsz) h0[idx] = hidden[idx];
}

__global__ void copy_k(const float* __restrict__ src, float* __restrict__ dst, int n)
{
    int i = blockIdx.x * blockDim.x + threadIdx.x;
    if (i < n) dst[i] = src[i];
}

// ======== log_softmax over V (in place), 512 threads, float4 ========
__global__ __launch_bounds__(512)
void lsm_k(float* __restrict__ out)
{
    __shared__ float red[16];
    float4* p = (float4*)(out + (size_t)blockIdx.x * Vsz);
    const int NV4 = Vsz / 4;  // 8000
    const int tid = threadIdx.x;

    float mx = -3.4e38f;
    for (int i = tid; i < NV4; i += 512) {
        float4 v = p[i];
        mx = fmaxf(mx, fmaxf(fmaxf(v.x, v.y), fmaxf(v.z, v.w)));
    }
    #pragma unroll
    for (int o = 16; o; o >>= 1) mx = fmaxf(mx, __shfl_xor_sync(0xffffffffu, mx, o));
    if ((tid & 31) == 0) red[tid >> 5] = mx;
    __syncthreads();
    mx = red[0];
    #pragma unroll
    for (int w = 1; w < 16; w++) mx = fmaxf(mx, red[w]);
    __syncthreads();

    float s = 0.f;
    for (int i = tid; i < NV4; i += 512) {
        float4 v = p[i];
        s += expf(v.x - mx) + expf(v.y - mx) + expf(v.z - mx) + expf(v.w - mx);
    }
    #pragma unroll
    for (int o = 16; o; o >>= 1) s += __shfl_xor_sync(0xffffffffu, s, o);
    if ((tid & 31) == 0) red[tid >> 5] = s;
    __syncthreads();
    s = 0.f;
    #pragma unroll
    for (int w = 0; w < 16; w++) s += red[w];
    const float lse = mx + logf(s);

    for (int i = tid; i < NV4; i += 512) {
        float4 v = p[i];
        v.x -= lse; v.y -= lse; v.z -= lse; v.w -= lse;
        p[i] = v;
    }
}

// ---------------- launch ----------------
extern "C" void kernel_launch(void* const* d_in, const int* in_sizes, int n_in,
                              void* d_out, int out_size)
{
    const float* enc    = (const float*)d_in[0];
    const float* hidden = (const float*)d_in[1];
    const int*   target = (const int*)  d_in[2];
    const float* embW   = (const float*)d_in[3];
    const float* Wa_w   = (const float*)d_in[4];
    const float* Wa_b   = (const float*)d_in[5];
    const float* Ua_w   = (const float*)d_in[6];
    const float* Ua_b   = (const float*)d_in[7];
    const float* Va_w   = (const float*)d_in[8];
    const float* Va_b   = (const float*)d_in[9];
    const float* W_ih   = (const float*)d_in[10];
    const float* W_hh   = (const float*)d_in[11];
    const float* b_ih   = (const float*)d_in[12];
    const float* b_hh   = (const float*)d_in[13];
    const float* out_W  = (const float*)d_in[14];
    const float* out_b  = (const float*)d_in[15];

    float* out_lp = (float*)d_out;                        // [B,T,V]
    float* out_h  = out_lp + (size_t)Bsz * Tsz * Vsz;     // [1,B,H]
    float* out_at = out_h + (size_t)Bsz * Hsz;            // [B,T,S]

    float *Uk, *h0, *hist, *xall, *qP, *giP, *ghP;
    cudaGetSymbolAddress((void**)&Uk,   g_Uk);
    cudaGetSymbolAddress((void**)&h0,   g_h0);
    cudaGetSymbolAddress((void**)&hist, g_hist);
    cudaGetSymbolAddress((void**)&xall, g_xall);
    cudaGetSymbolAddress((void**)&qP,   g_qp);
    cudaGetSymbolAddress((void**)&giP,  g_gip);
    cudaGetSymbolAddress((void**)&ghP,  g_ghp);

    // init: h0 copy + all T embedding gathers
    init_k<<<(Tsz * Bsz * Hsz) / 256, 256>>>(hidden, h0, embW, target, xall);

    // Uk = enc @ Ua_w^T + Ua_b   (M=8192, N=1024, K=1024)
    gemm_big<<<dim3(Hsz / 128, 1, (Bsz * Ssz) / 128), 256>>>(
        enc, Ua_w, Ua_b, Uk, Hsz, Hsz, 0);

    for (int t = 0; t < Tsz; t++) {
        const float* hc = (t == 0) ? h0 : hist + (size_t)(t - 1) * Bsz * Hsz;
        float* hn  = hist + (size_t)t * Bsz * Hsz;
        float* x_t = xall + (size_t)t * Bsz * 2 * Hsz;

        gemm_q_k<<<dim3(Hsz / 128, QSPL), 256>>>(hc, Wa_w, qP);
        attn_all_k<<<Bsz, 1024>>>(qP, Wa_b, Uk, Va_w, Va_b, enc, x_t, out_at, t);
        gemm_gru_k<<<dim3(H3 / 128, GSPL, 2), 256>>>(x_t, hc, W_ih, W_hh, giP, ghP);
        gates_k<<<(Bsz * Hsz) / 256, 256>>>(giP, ghP, b_ih, b_hh, hc, hn);
    }

    // batched logits: M = T*B = 640 (5 tiles), N = 32000; permuted epilogue.
    gemm_big<<<dim3(Vsz / 128, 1, (Tsz * Bsz) / 128), 256>>>(
        hist, out_W, out_b, out_lp, Hsz, Vsz, 1);

    copy_k<<<(Bsz * Hsz + 255) / 256, 256>>>(hist + (size_t)(Tsz - 1) * Bsz * Hsz,
                                             out_h, Bsz * Hsz);
    lsm_k<<<Bsz * Tsz, 512>>>(out_lp);
}

// round 5
// speedup vs baseline: 4.1244x; 1.2288x over previous
#include <cuda_runtime.h>
#include <math.h>
#include <stdint.h>

#define Bsz 64
#define Ssz 128
#define Hsz 1024
#define Vsz 32000
#define Tsz 10
#define H3  (3*Hsz)
#define QSPL 16
#define GSPL 8

#define BIG_SMEM   (2*(128+128)*36*4)
#define SMALL_SMEM (2*(64+128)*36*4)

// ---------------- device scratch ----------------
__device__ float g_Uk  [Bsz*Ssz*Hsz];
__device__ float g_h0  [Bsz*Hsz];
__device__ float g_hist[Tsz*Bsz*Hsz];
__device__ float g_xall[Tsz*Bsz*2*Hsz];
__device__ float g_qp  [QSPL*Bsz*Hsz];
__device__ float g_gip [GSPL*Bsz*H3];
__device__ float g_ghp [GSPL*Bsz*H3];
__device__ float g_sc  [Bsz*Ssz];

// ---------------- tf32 / cp.async helpers ----------------
__device__ __forceinline__ uint32_t to_tf32u(float x) {
    uint32_t u;
    asm("cvt.rna.tf32.f32 %0, %1;" : "=r"(u) : "f"(x));
    return u;
}

__device__ __forceinline__ void mma_tf32(float c[4],
                                         uint32_t a0, uint32_t a1, uint32_t a2, uint32_t a3,
                                         uint32_t b0, uint32_t b1)
{
    asm volatile(
        "mma.sync.aligned.m16n8k8.row.col.f32.tf32.tf32.f32 "
        "{%0,%1,%2,%3}, {%4,%5,%6,%7}, {%8,%9}, {%0,%1,%2,%3};"
        : "+f"(c[0]), "+f"(c[1]), "+f"(c[2]), "+f"(c[3])
        : "r"(a0), "r"(a1), "r"(a2), "r"(a3), "r"(b0), "r"(b1));
}

__device__ __forceinline__ void cp16(float* s, const float* g) {
    uint32_t sa = (uint32_t)__cvta_generic_to_shared(s);
    asm volatile("cp.async.cg.shared.global [%0], [%1], 16;\n"
                 :: "r"(sa), "l"(g) : "memory");
}
__device__ __forceinline__ void cp_commit() {
    asm volatile("cp.async.commit_group;\n" ::: "memory");
}
__device__ __forceinline__ void cp_wait0() {
    asm volatile("cp.async.wait_group 0;\n" ::: "memory");
}
__device__ __forceinline__ void cp_wait1() {
    asm volatile("cp.async.wait_group 1;\n" ::: "memory");
}

// ======== BIG GEMM: 128Mx128N, 8 warps (4Mx2N), warp 32x64, cp.async 2-stage ========
// C = A[M,K] @ W[N,K]^T + bias.  grid (N/128, 1, M/128), dyn smem BIG_SMEM.
__global__ __launch_bounds__(256)
void gemm_big(const float* __restrict__ A, const float* __restrict__ W,
              const float* __restrict__ bias, float* __restrict__ C,
              int K, int ldc, int permuteTB)
{
    extern __shared__ float sm[];
    float (*As)[36] = (float(*)[36])sm;                 // [2*128][36]
    float (*Bs)[36] = (float(*)[36])(sm + 2*128*36);    // [2*128][36]

    const int t    = threadIdx.x;
    const int lane = t & 31;
    const int wid  = t >> 5;
    const int wm32 = (wid & 3) * 32;
    const int wn64 = (wid >> 2) * 64;
    const int m0   = blockIdx.z * 128;
    const int n0   = blockIdx.x * 128;
    const int r    = lane >> 2;
    const int c    = lane & 3;

    float acc[2][8][4];
    #pragma unroll
    for (int mi = 0; mi < 2; mi++)
        #pragma unroll
        for (int nt = 0; nt < 8; nt++)
            #pragma unroll
            for (int j = 0; j < 4; j++) acc[mi][nt][j] = 0.f;

    // prologue stage chunk 0 -> buf 0
    #pragma unroll
    for (int rr = 0; rr < 4; rr++) {
        int idx = rr * 256 + t;
        int m = idx >> 3, kq = idx & 7;
        cp16(&As[m][kq << 2], A + (size_t)(m0 + m) * K + (kq << 2));
    }
    #pragma unroll
    for (int rr = 0; rr < 4; rr++) {
        int idx = rr * 256 + t;
        int n = idx >> 3, kq = idx & 7;
        cp16(&Bs[n][kq << 2], W + (size_t)(n0 + n) * K + (kq << 2));
    }
    cp_commit();

    const int niter = K >> 5;
    for (int i = 0; i < niter; i++) {
        const bool nxt = (i + 1 < niter);
        if (nxt) {
            const int kb = (i + 1) << 5;
            const int nb = ((i + 1) & 1) * 128;
            #pragma unroll
            for (int rr = 0; rr < 4; rr++) {
                int idx = rr * 256 + t;
                int m = idx >> 3, kq = idx & 7;
                cp16(&As[nb + m][kq << 2], A + (size_t)(m0 + m) * K + kb + (kq << 2));
            }
            #pragma unroll
            for (int rr = 0; rr < 4; rr++) {
                int idx = rr * 256 + t;
                int n = idx >> 3, kq = idx & 7;
                cp16(&Bs[nb + n][kq << 2], W + (size_t)(n0 + n) * K + kb + (kq << 2));
            }
            cp_commit();
            cp_wait1();
        } else {
            cp_wait0();
        }
        __syncthreads();

        const int ab = (i & 1) * 128;
        #pragma unroll
        for (int kc = 0; kc < 4; kc++) {
            const int k8 = kc << 3;
            uint32_t a[2][4];
            #pragma unroll
            for (int mi = 0; mi < 2; mi++) {
                const int mr = ab + wm32 + (mi << 4) + r;
                a[mi][0] = to_tf32u(As[mr    ][k8 + c    ]);
                a[mi][1] = to_tf32u(As[mr + 8][k8 + c    ]);
                a[mi][2] = to_tf32u(As[mr    ][k8 + c + 4]);
                a[mi][3] = to_tf32u(As[mr + 8][k8 + c + 4]);
            }
            #pragma unroll
            for (int nt = 0; nt < 8; nt++) {
                const int nr = ab + wn64 + (nt << 3) + r;
                uint32_t b0 = to_tf32u(Bs[nr][k8 + c    ]);
                uint32_t b1 = to_tf32u(Bs[nr][k8 + c + 4]);
                mma_tf32(acc[0][nt], a[0][0], a[0][1], a[0][2], a[0][3], b0, b1);
                mma_tf32(acc[1][nt], a[1][0], a[1][1], a[1][2], a[1][3], b0, b1);
            }
        }
        __syncthreads();
    }

    const int c2 = c << 1;
    #pragma unroll
    for (int mi = 0; mi < 2; mi++) {
        int mlog  = m0 + wm32 + (mi << 4) + r;
        int mlog2 = mlog + 8;
        int m  = permuteTB ? ((mlog  & 63) * Tsz + (mlog  >> 6)) : mlog;
        int m2 = permuteTB ? ((mlog2 & 63) * Tsz + (mlog2 >> 6)) : mlog2;
        #pragma unroll
        for (int nt = 0; nt < 8; nt++) {
            const int n = n0 + wn64 + (nt << 3) + c2;
            float b0 = bias[n], b1 = bias[n + 1];
            *(float2*)(C + (size_t)m  * ldc + n) =
                make_float2(acc[mi][nt][0] + b0, acc[mi][nt][1] + b1);
            *(float2*)(C + (size_t)m2 * ldc + n) =
                make_float2(acc[mi][nt][2] + b0, acc[mi][nt][3] + b1);
        }
    }
}

// ======== SMALL GEMM core: 64Mx128N, partial store, cp.async 2-stage ========
__device__ __forceinline__ void small_core(
    const float* __restrict__ A, const float* __restrict__ W, float* __restrict__ Cp,
    int K, int N, int kb0, int kPerSplit, int n0, float* sm)
{
    float (*As)[36] = (float(*)[36])sm;                // [2*64][36]
    float (*Bs)[36] = (float(*)[36])(sm + 2*64*36);    // [2*128][36]

    const int t    = threadIdx.x;
    const int lane = t & 31;
    const int wid  = t >> 5;
    const int wm16 = (wid & 3) * 16;
    const int wn64 = (wid >> 2) * 64;
    const int r    = lane >> 2;
    const int c    = lane & 3;

    float acc[8][4];
    #pragma unroll
    for (int i = 0; i < 8; i++)
        #pragma unroll
        for (int j = 0; j < 4; j++) acc[i][j] = 0.f;

    // prologue
    #pragma unroll
    for (int rr = 0; rr < 2; rr++) {
        int idx = rr * 256 + t;
        int m = idx >> 3, kq = idx & 7;
        cp16(&As[m][kq << 2], A + (size_t)m * K + kb0 + (kq << 2));
    }
    #pragma unroll
    for (int rr = 0; rr < 4; rr++) {
        int idx = rr * 256 + t;
        int n = idx >> 3, kq = idx & 7;
        cp16(&Bs[n][kq << 2], W + (size_t)(n0 + n) * K + kb0 + (kq << 2));
    }
    cp_commit();

    const int niter = kPerSplit >> 5;
    for (int i = 0; i < niter; i++) {
        const bool nxt = (i + 1 < niter);
        if (nxt) {
            const int kb = kb0 + ((i + 1) << 5);
            const int ao = ((i + 1) & 1) * 64;
            const int bo = ((i + 1) & 1) * 128;
            #pragma unroll
            for (int rr = 0; rr < 2; rr++) {
                int idx = rr * 256 + t;
                int m = idx >> 3, kq = idx & 7;
                cp16(&As[ao + m][kq << 2], A + (size_t)m * K + kb + (kq << 2));
            }
            #pragma unroll
            for (int rr = 0; rr < 4; rr++) {
                int idx = rr * 256 + t;
                int n = idx >> 3, kq = idx & 7;
                cp16(&Bs[bo + n][kq << 2], W + (size_t)(n0 + n) * K + kb + (kq << 2));
            }
            cp_commit();
            cp_wait1();
        } else {
            cp_wait0();
        }
        __syncthreads();

        const int ao = (i & 1) * 64;
        const int bo = (i & 1) * 128;
        #pragma unroll
        for (int kc = 0; kc < 4; kc++) {
            const int k8 = kc << 3;
            uint32_t a0 = to_tf32u(As[ao + wm16 + r    ][k8 + c    ]);
            uint32_t a1 = to_tf32u(As[ao + wm16 + r + 8][k8 + c    ]);
            uint32_t a2 = to_tf32u(As[ao + wm16 + r    ][k8 + c + 4]);
            uint32_t a3 = to_tf32u(As[ao + wm16 + r + 8][k8 + c + 4]);
            #pragma unroll
            for (int nt = 0; nt < 8; nt++) {
                const int nr = bo + wn64 + (nt << 3) + r;
                uint32_t b0 = to_tf32u(Bs[nr][k8 + c    ]);
                uint32_t b1 = to_tf32u(Bs[nr][k8 + c + 4]);
                mma_tf32(acc[nt], a0, a1, a2, a3, b0, b1);
            }
        }
        __syncthreads();
    }

    const int c2 = c << 1;
    #pragma unroll
    for (int nt = 0; nt < 8; nt++) {
        const int n = n0 + wn64 + (nt << 3) + c2;
        const int m = wm16 + r;
        *(float2*)(Cp + (size_t)m       * N + n) = make_float2(acc[nt][0], acc[nt][1]);
        *(float2*)(Cp + (size_t)(m + 8) * N + n) = make_float2(acc[nt][2], acc[nt][3]);
    }
}

// q partials: grid (Hsz/128, QSPL)
__global__ __launch_bounds__(256)
void gemm_q_k(const float* __restrict__ h, const float* __restrict__ Wa_w,
              float* __restrict__ qP)
{
    extern __shared__ float sm[];
    const int spl = blockIdx.y;
    const int kps = Hsz / QSPL;
    small_core(h, Wa_w, qP + (size_t)spl * Bsz * Hsz,
               Hsz, Hsz, spl * kps, kps, blockIdx.x * 128, sm);
}

// gi/gh partials: grid (H3/128, GSPL, 2)
__global__ __launch_bounds__(256)
void gemm_gru_k(const float* __restrict__ x_t, const float* __restrict__ h,
                const float* __restrict__ W_ih, const float* __restrict__ W_hh,
                float* __restrict__ giP, float* __restrict__ ghP)
{
    extern __shared__ float sm[];
    const int spl = blockIdx.y;
    const int z = blockIdx.z;
    const float* A = z ? h : x_t;
    const float* W = z ? W_hh : W_ih;
    float* Cp = (z ? ghP : giP) + (size_t)spl * Bsz * H3;
    const int K = z ? Hsz : 2 * Hsz;
    const int kps = K / GSPL;
    small_core(A, W, Cp, K, H3, spl * kps, kps, blockIdx.x * 128, sm);
}

// ======== scores: q-reduce + Va.tanh(q+Uk), grid (B, 4), warp-per-s ========
__global__ __launch_bounds__(1024)
void scores_k(const float* __restrict__ qP, const float* __restrict__ Wa_b,
              const float* __restrict__ Uk, const float* __restrict__ Va,
              const float* __restrict__ Vab, float* __restrict__ scores)
{
    __shared__ __align__(16) float qs[Hsz];
    const int b = blockIdx.x, tid = threadIdx.x;
    const int w = tid >> 5, lane = tid & 31;

    float qacc = Wa_b[tid];
    #pragma unroll
    for (int p = 0; p < QSPL; p++) qacc += qP[(size_t)p * Bsz * Hsz + b * Hsz + tid];
    qs[tid] = qacc;
    __syncthreads();

    const int s = blockIdx.y * 32 + w;
    const float* ukr = Uk + ((size_t)b * Ssz + s) * Hsz;
    float a = 0.f;
    #pragma unroll
    for (int j = 0; j < 8; j++) {
        const int hh = lane * 4 + j * 128;
        float4 u  = *(const float4*)(ukr + hh);
        float4 qv = *(const float4*)(&qs[hh]);
        float4 vv = *(const float4*)(Va + hh);
        a += vv.x * tanhf(qv.x + u.x);
        a += vv.y * tanhf(qv.y + u.y);
        a += vv.z * tanhf(qv.z + u.z);
        a += vv.w * tanhf(qv.w + u.w);
    }
    #pragma unroll
    for (int o = 16; o; o >>= 1) a += __shfl_xor_sync(0xffffffffu, a, o);
    if (!lane) scores[b * Ssz + s] = a + Vab[0];
}

// ======== ctx: softmax (recomputed per block) + weighted sum, grid (B, 8) ========
__global__ __launch_bounds__(128)
void ctx_k(const float* __restrict__ sc, const float* __restrict__ E,
           float* __restrict__ x_t, float* __restrict__ attns, int t)
{
    __shared__ float wsm[Ssz];
    __shared__ float red[4];
    const int b = blockIdx.x, tid = threadIdx.x;

    float v0 = sc[b * Ssz + tid];
    float m = v0;
    #pragma unroll
    for (int o = 16; o; o >>= 1) m = fmaxf(m, __shfl_xor_sync(0xffffffffu, m, o));
    if ((tid & 31) == 0) red[tid >> 5] = m;
    __syncthreads();
    float mx = fmaxf(fmaxf(red[0], red[1]), fmaxf(red[2], red[3]));
    __syncthreads();

    float e = expf(v0 - mx);
    float smv = e;
    #pragma unroll
    for (int o = 16; o; o >>= 1) smv += __shfl_xor_sync(0xffffffffu, smv, o);
    if ((tid & 31) == 0) red[tid >> 5] = smv;
    __syncthreads();
    float ssum = red[0] + red[1] + red[2] + red[3];

    float w = e / ssum;
    wsm[tid] = w;
    if (blockIdx.y == 0) attns[((size_t)b * Tsz + t) * Ssz + tid] = w;
    __syncthreads();

    const int h = blockIdx.y * 128 + tid;
    const float* Eb = E + (size_t)b * Ssz * Hsz + h;
    float acc = 0.f;
    #pragma unroll 8
    for (int s2 = 0; s2 < Ssz; s2++) acc = fmaf(wsm[s2], Eb[(size_t)s2 * Hsz], acc);
    x_t[b * 2 * Hsz + Hsz + h] = acc;
}

// ======== GRU gates: reduce partials + nonlinearity ========
__global__ void gates_k(const float* __restrict__ giP, const float* __restrict__ ghP,
                        const float* __restrict__ b_ih, const float* __restrict__ b_hh,
                        const float* __restrict__ hin, float* __restrict__ hout)
{
    const int idx = blockIdx.x * 256 + threadIdx.x;
    const int b = idx >> 10, j = idx & 1023;
    float gir = b_ih[j], giz = b_ih[Hsz + j], gin = b_ih[2 * Hsz + j];
    float ghr = b_hh[j], ghz = b_hh[Hsz + j], ghn = b_hh[2 * Hsz + j];
    const int base = b * H3 + j;
    #pragma unroll
    for (int p = 0; p < GSPL; p++) {
        const float* gp = giP + (size_t)p * Bsz * H3 + base;
        gir += gp[0]; giz += gp[Hsz]; gin += gp[2 * Hsz];
        const float* hp = ghP + (size_t)p * Bsz * H3 + base;
        ghr += hp[0]; ghz += hp[Hsz]; ghn += hp[2 * Hsz];
    }
    float r = 1.f / (1.f + expf(-(gir + ghr)));
    float z = 1.f / (1.f + expf(-(giz + ghz)));
    float n = tanhf(gin + r * ghn);
    hout[idx] = (1.f - z) * n + z * hin[idx];
}

// ======== init + copy + log_softmax ========
__global__ void init_k(const float* __restrict__ hidden, float* __restrict__ h0,
                       const float* __restrict__ embW, const int* __restrict__ target,
                       float* __restrict__ xall)
{
    const int idx = blockIdx.x * 256 + threadIdx.x;
    const int t = idx / (Bsz * Hsz);
    const int rem = idx - t * (Bsz * Hsz);
    const int b = rem >> 10, h = rem & 1023;
    const int tok = (t == 0) ? 0 : target[b * Tsz + (t - 1)];
    xall[(size_t)t * Bsz * 2 * Hsz + b * 2 * Hsz + h] = embW[(size_t)tok * Hsz + h];
    if (idx < Bsz * Hsz) h0[idx] = hidden[idx];
}

__global__ void copy_k(const float* __restrict__ src, float* __restrict__ dst, int n)
{
    int i = blockIdx.x * blockDim.x + threadIdx.x;
    if (i < n) dst[i] = src[i];
}

__global__ __launch_bounds__(512)
void lsm_k(float* __restrict__ out)
{
    __shared__ float red[16];
    float4* p = (float4*)(out + (size_t)blockIdx.x * Vsz);
    const int NV4 = Vsz / 4;
    const int tid = threadIdx.x;

    float mx = -3.4e38f;
    for (int i = tid; i < NV4; i += 512) {
        float4 v = p[i];
        mx = fmaxf(mx, fmaxf(fmaxf(v.x, v.y), fmaxf(v.z, v.w)));
    }
    #pragma unroll
    for (int o = 16; o; o >>= 1) mx = fmaxf(mx, __shfl_xor_sync(0xffffffffu, mx, o));
    if ((tid & 31) == 0) red[tid >> 5] = mx;
    __syncthreads();
    mx = red[0];
    #pragma unroll
    for (int w = 1; w < 16; w++) mx = fmaxf(mx, red[w]);
    __syncthreads();

    float s = 0.f;
    for (int i = tid; i < NV4; i += 512) {
        float4 v = p[i];
        s += expf(v.x - mx) + expf(v.y - mx) + expf(v.z - mx) + expf(v.w - mx);
    }
    #pragma unroll
    for (int o = 16; o; o >>= 1) s += __shfl_xor_sync(0xffffffffu, s, o);
    if ((tid & 31) == 0) red[tid >> 5] = s;
    __syncthreads();
    s = 0.f;
    #pragma unroll
    for (int w = 0; w < 16; w++) s += red[w];
    const float lse = mx + logf(s);

    for (int i = tid; i < NV4; i += 512) {
        float4 v = p[i];
        v.x -= lse; v.y -= lse; v.z -= lse; v.w -= lse;
        p[i] = v;
    }
}

// ---------------- launch ----------------
extern "C" void kernel_launch(void* const* d_in, const int* in_sizes, int n_in,
                              void* d_out, int out_size)
{
    const float* enc    = (const float*)d_in[0];
    const float* hidden = (const float*)d_in[1];
    const int*   target = (const int*)  d_in[2];
    const float* embW   = (const float*)d_in[3];
    const float* Wa_w   = (const float*)d_in[4];
    const float* Wa_b   = (const float*)d_in[5];
    const float* Ua_w   = (const float*)d_in[6];
    const float* Ua_b   = (const float*)d_in[7];
    const float* Va_w   = (const float*)d_in[8];
    const float* Va_b   = (const float*)d_in[9];
    const float* W_ih   = (const float*)d_in[10];
    const float* W_hh   = (const float*)d_in[11];
    const float* b_ih   = (const float*)d_in[12];
    const float* b_hh   = (const float*)d_in[13];
    const float* out_W  = (const float*)d_in[14];
    const float* out_b  = (const float*)d_in[15];

    float* out_lp = (float*)d_out;                        // [B,T,V]
    float* out_h  = out_lp + (size_t)Bsz * Tsz * Vsz;     // [1,B,H]
    float* out_at = out_h + (size_t)Bsz * Hsz;            // [B,T,S]

    float *Uk, *h0, *hist, *xall, *qP, *giP, *ghP, *sc;
    cudaGetSymbolAddress((void**)&Uk,   g_Uk);
    cudaGetSymbolAddress((void**)&h0,   g_h0);
    cudaGetSymbolAddress((void**)&hist, g_hist);
    cudaGetSymbolAddress((void**)&xall, g_xall);
    cudaGetSymbolAddress((void**)&qP,   g_qp);
    cudaGetSymbolAddress((void**)&giP,  g_gip);
    cudaGetSymbolAddress((void**)&ghP,  g_ghp);
    cudaGetSymbolAddress((void**)&sc,   g_sc);

    // opt-in smem (host-side, runs at capture only — not a graph op)
    cudaFuncSetAttribute(gemm_big,   cudaFuncAttributeMaxDynamicSharedMemorySize, BIG_SMEM);
    cudaFuncSetAttribute(gemm_q_k,   cudaFuncAttributeMaxDynamicSharedMemorySize, SMALL_SMEM);
    cudaFuncSetAttribute(gemm_gru_k, cudaFuncAttributeMaxDynamicSharedMemorySize, SMALL_SMEM);

    init_k<<<(Tsz * Bsz * Hsz) / 256, 256>>>(hidden, h0, embW, target, xall);

    // Uk = enc @ Ua_w^T + Ua_b
    gemm_big<<<dim3(Hsz / 128, 1, (Bsz * Ssz) / 128), 256, BIG_SMEM>>>(
        enc, Ua_w, Ua_b, Uk, Hsz, Hsz, 0);

    for (int t = 0; t < Tsz; t++) {
        const float* hc = (t == 0) ? h0 : hist + (size_t)(t - 1) * Bsz * Hsz;
        float* hn  = hist + (size_t)t * Bsz * Hsz;
        float* x_t = xall + (size_t)t * Bsz * 2 * Hsz;

        gemm_q_k<<<dim3(Hsz / 128, QSPL), 256, SMALL_SMEM>>>(hc, Wa_w, qP);
        scores_k<<<dim3(Bsz, 4), 1024>>>(qP, Wa_b, Uk, Va_w, Va_b, sc);
        ctx_k<<<dim3(Bsz, Hsz / 128), 128>>>(sc, enc, x_t, out_at, t);
        gemm_gru_k<<<dim3(H3 / 128, GSPL, 2), 256, SMALL_SMEM>>>(x_t, hc, W_ih, W_hh, giP, ghP);
        gates_k<<<(Bsz * Hsz) / 256, 256>>>(giP, ghP, b_ih, b_hh, hc, hn);
    }

    // batched logits (permuted epilogue), out_W read once
    gemm_big<<<dim3(Vsz / 128, 1, (Tsz * Bsz) / 128), 256, BIG_SMEM>>>(
        hist, out_W, out_b, out_lp, Hsz, Vsz, 1);

    copy_k<<<(Bsz * Hsz + 255) / 256, 256>>>(hist + (size_t)(Tsz - 1) * Bsz * Hsz,
                                             out_h, Bsz * Hsz);
    lsm_k<<<Bsz * Tsz, 512>>>(out_lp);
}